// round 13
// baseline (speedup 1.0000x reference)
#include <cuda_runtime.h>
#include <cuda_bf16.h>
#include <cstdint>

// ActuatorNet, round 13: heterogeneous warp specialization.
// Per 384-thread CTA (2 CTAs/SM, 24 warps/SM, 85-reg cap):
//   warps 0-7 : HMMA bf16 hi/lo 3-term path (champion structure, R12 body)
//               on rows [0, B_h)  (~89% of rows)
//   warps 8-11: FFMA2 (packed fp32x2) path, 1 row/thread, weights __ldg
//               from global fp32 (broadcast, L1/L2-resident) on [B_h, B)
// Different pipes (tensor vs fma) + decorrelated stalls -> higher issue eff.

#define NTHREADS 384
#define HWARPS   8          // HMMA warps per CTA
#define FWARPS   4          // FFMA2 warps per CTA

typedef unsigned long long u64;

// smem layout (bytes)
#define SM_FRAG   0                      // 19*16*32 u64 = 77824
#define SM_W1     77824                  // 192 f32
#define SM_B1     (SM_W1 + 768)          // 32 f32
#define SM_BH     (SM_B1 + 128)          // 19*32 f32 = 2432
#define SM_WOUT   (SM_BH + 2432)         // 32 f32
#define SM_BOUT   (SM_WOUT + 128)        // 1 f32
#define SM_TOTAL  (SM_BOUT + 16)         // ~81.2 KB -> 2 CTAs/SM

__device__ __forceinline__ uint32_t cvt_bf16x2(float hi_elem, float lo_elem) {
    uint32_t r;
    asm("cvt.rn.bf16x2.f32 %0, %1, %2;" : "=r"(r) : "f"(hi_elem), "f"(lo_elem));
    return r;
}

__device__ __forceinline__ void mma_bf16(float* d,
                                         uint32_t a0, uint32_t a1,
                                         uint32_t a2, uint32_t a3,
                                         uint32_t b0, uint32_t b1) {
    asm volatile(
        "mma.sync.aligned.m16n8k16.row.col.f32.bf16.bf16.f32 "
        "{%0,%1,%2,%3}, {%4,%5,%6,%7}, {%8,%9}, {%0,%1,%2,%3};"
        : "+f"(d[0]), "+f"(d[1]), "+f"(d[2]), "+f"(d[3])
        : "r"(a0), "r"(a1), "r"(a2), "r"(a3), "r"(b0), "r"(b1));
}

__device__ __forceinline__ float softsign_f(float v) {
    return __fdividef(v, 1.0f + fabsf(v));
}

__device__ __forceinline__ void ss_split(const float* acc,
                                         uint32_t* ahi, uint32_t* alo) {
    #pragma unroll
    for (int p = 0; p < 8; p++) {
        float e0 = softsign_f(acc[2 * p]);
        float e1 = softsign_f(acc[2 * p + 1]);
        uint32_t hp = cvt_bf16x2(e1, e0);
        float f0 = __uint_as_float(hp << 16);
        float f1 = __uint_as_float(hp & 0xFFFF0000u);
        ahi[p] = hp;
        alo[p] = cvt_bf16x2(e1 - f1, e0 - f0);
    }
}

__device__ __forceinline__ void mma_phase(float* acc0, float* acc1,
                                          const u64* fl, int slot,
                                          const uint32_t* a0v,
                                          const uint32_t* a1v) {
    u64 Bf[4];
    #pragma unroll
    for (int nb = 0; nb < 4; nb++) Bf[nb] = fl[(slot + nb) * 32];
    #pragma unroll
    for (int nb = 0; nb < 4; nb++) {
        uint32_t b0 = (uint32_t)Bf[nb], b1 = (uint32_t)(Bf[nb] >> 32);
        mma_bf16(acc0 + nb * 4, a0v[0], a0v[1], a0v[2], a0v[3], b0, b1);
        mma_bf16(acc1 + nb * 4, a1v[0], a1v[1], a1v[2], a1v[3], b0, b1);
    }
}

// ---- FFMA2 helpers (packed fp32x2, from round-2 winner) ----
__device__ __forceinline__ u64 dup2(float v) {
    u64 r;
    asm("mov.b64 %0, {%1, %1};" : "=l"(r) : "f"(v));
    return r;
}
__device__ __forceinline__ void fma2(u64& d, u64 a, u64 b) {
    asm("fma.rn.f32x2 %0, %1, %2, %0;" : "+l"(d) : "l"(a), "l"(b));
}
__device__ __forceinline__ float2 unpk(u64 v) {
    float2 f;
    asm("mov.b64 {%0, %1}, %2;" : "=f"(f.x), "=f"(f.y) : "l"(v));
    return f;
}

__global__ __launch_bounds__(NTHREADS, 2)
void actuator_hybrid_kernel(const float* __restrict__ x,
                            const float* __restrict__ W1,
                            const float* __restrict__ b1,
                            const float* __restrict__ Wh,
                            const float* __restrict__ bh,
                            const float* __restrict__ Wout,
                            const float* __restrict__ bout,
                            float* __restrict__ out,
                            int B, int B_h, int npairs_h)
{
    extern __shared__ char smem[];
    u64*   sFRAG = (u64*)(smem + SM_FRAG);
    float* sW1   = (float*)(smem + SM_W1);
    float* sB1   = (float*)(smem + SM_B1);
    float* sBH   = (float*)(smem + SM_BH);
    float* sWOUT = (float*)(smem + SM_WOUT);
    float* sBOUT = (float*)(smem + SM_BOUT);

    const int tid = threadIdx.x;

    for (int i = tid; i < 192; i += NTHREADS) sW1[i] = W1[i];
    for (int i = tid; i < 32;  i += NTHREADS) sB1[i] = b1[i];
    for (int i = tid; i < 608; i += NTHREADS) sBH[i] = bh[i];
    for (int i = tid; i < 32;  i += NTHREADS) sWOUT[i] = Wout[i];
    if (tid == 0) sBOUT[0] = bout[0];

    // stage hidden weights as per-thread B fragments (hi & lo)
    for (int idx = tid; idx < 19 * 16 * 32; idx += NTHREADS) {
        int lane  = idx & 31;
        int combo = (idx >> 5) & 15;
        int l     = idx >> 9;
        int nb    = combo & 3;
        int ks    = (combo >> 2) & 1;
        int term  = combo >> 3;
        int col   = nb * 8 + (lane >> 2);
        int qq    = lane & 3;
        int k0    = ks * 16 + qq * 2;

        const float* Wl = Wh + l * 1024;
        float w0 = Wl[(k0 + 0) * 32 + col];
        float w1 = Wl[(k0 + 1) * 32 + col];
        float w2 = Wl[(k0 + 8) * 32 + col];
        float w3 = Wl[(k0 + 9) * 32 + col];

        uint32_t rb0, rb1;
        if (term == 0) {
            rb0 = cvt_bf16x2(w1, w0);
            rb1 = cvt_bf16x2(w3, w2);
        } else {
            float r0 = w0 - __bfloat162float(__float2bfloat16(w0));
            float r1 = w1 - __bfloat162float(__float2bfloat16(w1));
            float r2 = w2 - __bfloat162float(__float2bfloat16(w2));
            float r3 = w3 - __bfloat162float(__float2bfloat16(w3));
            rb0 = cvt_bf16x2(r1, r0);
            rb1 = cvt_bf16x2(r3, r2);
        }
        sFRAG[idx] = ((u64)rb1 << 32) | rb0;
    }
    __syncthreads();

    const int wid  = tid >> 5;
    const int lane = tid & 31;
    const float bias_out = sBOUT[0];

    if (wid < HWARPS) {
        // ================= HMMA path: rows [0, B_h) =================
        const int g = lane >> 2;
        const int q = lane & 3;

        for (int pair = blockIdx.x * HWARPS + wid; pair < npairs_h;
             pair += gridDim.x * HWARPS) {

            int base = pair * 32;
            int rA0 = base + g,      rA1 = base + 8 + g;
            int rB0 = base + 16 + g, rB1 = base + 24 + g;

            float acc0[16], acc1[16];

            // layer 1 (6 -> 32), raw preactivations
            {
                float x0[6], x1[6], x2[6], x3[6];
                const float* p0 = x + (long long)rA0 * 6;
                const float* p1 = x + (long long)rA1 * 6;
                const float* p2 = x + (long long)rB0 * 6;
                const float* p3 = x + (long long)rB1 * 6;
                #pragma unroll
                for (int i = 0; i < 6; i++) {
                    x0[i] = __ldg(p0 + i); x1[i] = __ldg(p1 + i);
                    x2[i] = __ldg(p2 + i); x3[i] = __ldg(p3 + i);
                }
                #pragma unroll
                for (int nb = 0; nb < 4; nb++) {
                    int c0 = nb * 8 + q * 2;
                    float b0 = sB1[c0], b1v = sB1[c0 + 1];
                    float s00 = b0, s01 = b1v, s10 = b0, s11 = b1v;
                    float t00 = b0, t01 = b1v, t10 = b0, t11 = b1v;
                    #pragma unroll
                    for (int i = 0; i < 6; i++) {
                        float w0 = sW1[i * 32 + c0], w1 = sW1[i * 32 + c0 + 1];
                        s00 += x0[i] * w0; s01 += x0[i] * w1;
                        s10 += x1[i] * w0; s11 += x1[i] * w1;
                        t00 += x2[i] * w0; t01 += x2[i] * w1;
                        t10 += x3[i] * w0; t11 += x3[i] * w1;
                    }
                    acc0[nb*4+0] = s00; acc0[nb*4+1] = s01;
                    acc0[nb*4+2] = s10; acc0[nb*4+3] = s11;
                    acc1[nb*4+0] = t00; acc1[nb*4+1] = t01;
                    acc1[nb*4+2] = t10; acc1[nb*4+3] = t11;
                }
            }

            // 19 hidden layers via HMMA
            for (int l = 0; l < 19; l++) {
                uint32_t ahi0[8], alo0[8], ahi1[8], alo1[8];
                ss_split(acc0, ahi0, alo0);
                ss_split(acc1, ahi1, alo1);

                const float2* blp = (const float2*)(sBH + l * 32);
                #pragma unroll
                for (int nb = 0; nb < 4; nb++) {
                    float2 bb = blp[nb * 4 + q];
                    acc0[nb*4+0] = bb.x; acc0[nb*4+1] = bb.y;
                    acc0[nb*4+2] = bb.x; acc0[nb*4+3] = bb.y;
                    acc1[nb*4+0] = bb.x; acc1[nb*4+1] = bb.y;
                    acc1[nb*4+2] = bb.x; acc1[nb*4+3] = bb.y;
                }

                const u64* fl = sFRAG + l * 512 + lane;
                mma_phase(acc0, acc1, fl, 0,  ahi0 + 0, ahi1 + 0);
                mma_phase(acc0, acc1, fl, 4,  ahi0 + 4, ahi1 + 4);
                mma_phase(acc0, acc1, fl, 0,  alo0 + 0, alo1 + 0);
                mma_phase(acc0, acc1, fl, 4,  alo0 + 4, alo1 + 4);
                mma_phase(acc0, acc1, fl, 8,  ahi0 + 0, ahi1 + 0);
                mma_phase(acc0, acc1, fl, 12, ahi0 + 4, ahi1 + 4);
            }

            // final softsign + output layer + quad reduction
            float pA0 = 0.0f, pA1 = 0.0f, pB0 = 0.0f, pB1 = 0.0f;
            #pragma unroll
            for (int nb = 0; nb < 4; nb++) {
                int c0 = nb * 8 + q * 2;
                float w0 = sWOUT[c0], w1 = sWOUT[c0 + 1];
                pA0 += softsign_f(acc0[nb*4+0]) * w0 + softsign_f(acc0[nb*4+1]) * w1;
                pA1 += softsign_f(acc0[nb*4+2]) * w0 + softsign_f(acc0[nb*4+3]) * w1;
                pB0 += softsign_f(acc1[nb*4+0]) * w0 + softsign_f(acc1[nb*4+1]) * w1;
                pB1 += softsign_f(acc1[nb*4+2]) * w0 + softsign_f(acc1[nb*4+3]) * w1;
            }
            pA0 += __shfl_xor_sync(0xFFFFFFFFu, pA0, 1);
            pA0 += __shfl_xor_sync(0xFFFFFFFFu, pA0, 2);
            pA1 += __shfl_xor_sync(0xFFFFFFFFu, pA1, 1);
            pA1 += __shfl_xor_sync(0xFFFFFFFFu, pA1, 2);
            pB0 += __shfl_xor_sync(0xFFFFFFFFu, pB0, 1);
            pB0 += __shfl_xor_sync(0xFFFFFFFFu, pB0, 2);
            pB1 += __shfl_xor_sync(0xFFFFFFFFu, pB1, 1);
            pB1 += __shfl_xor_sync(0xFFFFFFFFu, pB1, 2);
            if (q == 0) {
                out[rA0] = pA0 + bias_out;
                out[rA1] = pA1 + bias_out;
                out[rB0] = pB0 + bias_out;
                out[rB1] = pB1 + bias_out;
            }
        }
    } else {
        // ================= FFMA2 path: rows [B_h, B) =================
        const int fslot = blockIdx.x * FWARPS + (wid - HWARPS);
        const int fstride = gridDim.x * FWARPS * 32;

        for (int row = B_h + fslot * 32 + lane; row < B; row += fstride) {

            float h[32];

            // layer 1 (6 -> 32) scalar fp32
            {
                float xin[6];
                const float* xr = x + (long long)row * 6;
                #pragma unroll
                for (int i = 0; i < 6; i++) xin[i] = __ldg(xr + i);
                #pragma unroll
                for (int j = 0; j < 32; j++) h[j] = sB1[j];
                #pragma unroll
                for (int i = 0; i < 6; i++) {
                    float xi = xin[i];
                    #pragma unroll
                    for (int j = 0; j < 32; j++) h[j] += xi * sW1[i * 32 + j];
                }
                #pragma unroll
                for (int j = 0; j < 32; j++) h[j] = softsign_f(h[j]);
            }

            // 19 hidden layers: packed fp32x2 FMA, weights via __ldg
            for (int l = 0; l < 19; l++) {
                const float* Wl = Wh + l * 1024;
                const float* bl = sBH + l * 32;

                u64 acc[16];
                #pragma unroll
                for (int p = 0; p < 16; p++) {
                    u64 a;
                    asm("mov.b64 %0, {%1, %2};" : "=l"(a)
                        : "f"(bl[2 * p]), "f"(bl[2 * p + 1]));
                    acc[p] = a;
                }
                #pragma unroll
                for (int i = 0; i < 32; i++) {
                    u64 mi = dup2(h[i]);
                    const ulonglong2* wr =
                        reinterpret_cast<const ulonglong2*>(Wl + i * 32);
                    #pragma unroll
                    for (int q4 = 0; q4 < 8; q4++) {
                        ulonglong2 w = __ldg(wr + q4);
                        fma2(acc[2 * q4],     mi, w.x);
                        fma2(acc[2 * q4 + 1], mi, w.y);
                    }
                }
                #pragma unroll
                for (int p = 0; p < 16; p++) {
                    float2 v = unpk(acc[p]);
                    h[2 * p]     = softsign_f(v.x);
                    h[2 * p + 1] = softsign_f(v.y);
                }
            }

            // output layer
            float o = bias_out;
            #pragma unroll
            for (int i = 0; i < 32; i++) o += h[i] * sWOUT[i];
            out[row] = o;
        }
    }
}

extern "C" void kernel_launch(void* const* d_in, const int* in_sizes, int n_in,
                              void* d_out, int out_size)
{
    const float* x    = (const float*)d_in[0];
    const float* W1   = (const float*)d_in[1];
    const float* b1   = (const float*)d_in[2];
    const float* Wh   = (const float*)d_in[3];
    const float* bh   = (const float*)d_in[4];
    const float* Wout = (const float*)d_in[5];
    const float* bout = (const float*)d_in[6];
    float* out = (float*)d_out;

    int B = in_sizes[0] / 6;

    // static split: ~11% of rows to the FFMA2 warps (multiple of 32);
    // HMMA side gets a multiple of 32 so its pair tiles never cross B_h.
    int B_f = (int)(((long long)B * 11) / 100) & ~31;
    int B_h = B - B_f;
    int npairs_h = B_h / 32;          // B is a multiple of 32 here
    // safety for general B: fold any remainder into the FFMA side
    if (npairs_h * 32 > B_h) npairs_h--;

    cudaFuncSetAttribute(actuator_hybrid_kernel,
                         cudaFuncAttributeMaxDynamicSharedMemorySize, SM_TOTAL);

    int grid = 296;   // persistent: 2 CTAs/SM x 148 SMs
    actuator_hybrid_kernel<<<grid, NTHREADS, SM_TOTAL>>>(
        x, W1, b1, Wh, bh, Wout, bout, out, B, B_h, npairs_h);
}

// round 14
// speedup vs baseline: 3.1518x; 3.1518x over previous
#include <cuda_runtime.h>
#include <cuda_fp16.h>
#include <cstdint>

// ActuatorNet, round 14: PURE fp16 HMMA — no hi/lo split.
// Error model (validated in R4-R13: bf16 3-term predicted ~2e-5, measured
// 1.45e-5): fp16 quantization of activations+weights gives ~2e-4/layer,
// softsign contraction ~0.5 -> final rel_err ~4e-4 < 1e-3 threshold.
// Structural payoff: per pair-layer MMAs 48->16, LDS 16->8, epilogue loses
// all lo-extraction. Issue census ~300 -> ~150.
// Shape: champion config (256 thr, 2 CTA/SM, 8 warps, 2 tiles/warp,
// term-major MMA order, bias via MMA C operand).

#define NTHREADS 256
#define NWARPS   8

typedef unsigned long long u64;

// smem layout (bytes)
#define SM_FRAG   0                      // 19*8*32 u64 = 38912
#define SM_W1     38912                  // 192 f32
#define SM_B1     (SM_W1 + 768)          // 32 f32
#define SM_BH     (SM_B1 + 128)          // 19*32 f32 = 2432
#define SM_WOUT   (SM_BH + 2432)         // 32 f32
#define SM_BOUT   (SM_WOUT + 128)        // 1 f32
#define SM_TOTAL  (SM_BOUT + 16)         // ~42.3 KB -> 2 CTAs/SM easily

// pack (hi_elem -> upper half, lo_elem -> lower half) as fp16x2
__device__ __forceinline__ uint32_t cvt_f16x2(float hi_elem, float lo_elem) {
    uint32_t r;
    asm("cvt.rn.f16x2.f32 %0, %1, %2;" : "=r"(r) : "f"(hi_elem), "f"(lo_elem));
    return r;
}

// d += a*b   (fp16 inputs, f32 accumulate)
__device__ __forceinline__ void mma_f16(float* d,
                                        uint32_t a0, uint32_t a1,
                                        uint32_t a2, uint32_t a3,
                                        uint32_t b0, uint32_t b1) {
    asm volatile(
        "mma.sync.aligned.m16n8k16.row.col.f32.f16.f16.f32 "
        "{%0,%1,%2,%3}, {%4,%5,%6,%7}, {%8,%9}, {%0,%1,%2,%3};"
        : "+f"(d[0]), "+f"(d[1]), "+f"(d[2]), "+f"(d[3])
        : "r"(a0), "r"(a1), "r"(a2), "r"(a3), "r"(b0), "r"(b1));
}

// d = a*b + {cx,cy,cx,cy}  (bias init via C operand)
__device__ __forceinline__ void mma_f16_init(float* d,
                                             uint32_t a0, uint32_t a1,
                                             uint32_t a2, uint32_t a3,
                                             uint32_t b0, uint32_t b1,
                                             float cx, float cy) {
    asm volatile(
        "mma.sync.aligned.m16n8k16.row.col.f32.f16.f16.f32 "
        "{%0,%1,%2,%3}, {%4,%5,%6,%7}, {%8,%9}, {%10,%11,%10,%11};"
        : "=f"(d[0]), "=f"(d[1]), "=f"(d[2]), "=f"(d[3])
        : "r"(a0), "r"(a1), "r"(a2), "r"(a3), "r"(b0), "r"(b1),
          "f"(cx), "f"(cy));
}

__device__ __forceinline__ float softsign_f(float v) {
    return __fdividef(v, 1.0f + fabsf(v));
}

// softsign(raw acc) then pack to fp16 A fragments (no lo term).
__device__ __forceinline__ void ss_pack(const float* acc, uint32_t* a) {
    #pragma unroll
    for (int p = 0; p < 8; p++) {
        float e0 = softsign_f(acc[2 * p]);
        float e1 = softsign_f(acc[2 * p + 1]);
        a[p] = cvt_f16x2(e1, e0);
    }
}

__global__ __launch_bounds__(NTHREADS, 2)
void actuator_hmma_kernel(const float* __restrict__ x,
                          const float* __restrict__ W1,
                          const float* __restrict__ b1,
                          const float* __restrict__ Wh,
                          const float* __restrict__ bh,
                          const float* __restrict__ Wout,
                          const float* __restrict__ bout,
                          float* __restrict__ out,
                          int B, int npairs)
{
    extern __shared__ char smem[];
    u64*   sFRAG = (u64*)(smem + SM_FRAG);
    float* sW1   = (float*)(smem + SM_W1);
    float* sB1   = (float*)(smem + SM_B1);
    float* sBH   = (float*)(smem + SM_BH);
    float* sWOUT = (float*)(smem + SM_WOUT);
    float* sBOUT = (float*)(smem + SM_BOUT);

    const int tid = threadIdx.x;

    for (int i = tid; i < 192; i += NTHREADS) sW1[i] = W1[i];
    for (int i = tid; i < 32;  i += NTHREADS) sB1[i] = b1[i];
    for (int i = tid; i < 608; i += NTHREADS) sBH[i] = bh[i];
    for (int i = tid; i < 32;  i += NTHREADS) sWOUT[i] = Wout[i];
    if (tid == 0) sBOUT[0] = bout[0];

    // stage hidden weights as per-thread fp16 B fragments
    // slot = ((l*8 + combo)*32 + lane), combo = ks*4 + nb
    for (int idx = tid; idx < 19 * 8 * 32; idx += NTHREADS) {
        int lane  = idx & 31;
        int combo = (idx >> 5) & 7;
        int l     = idx >> 8;
        int nb    = combo & 3;
        int ks    = combo >> 2;
        int col   = nb * 8 + (lane >> 2);
        int qq    = lane & 3;
        int k0    = ks * 16 + qq * 2;

        const float* Wl = Wh + l * 1024;
        float w0 = Wl[(k0 + 0) * 32 + col];
        float w1 = Wl[(k0 + 1) * 32 + col];
        float w2 = Wl[(k0 + 8) * 32 + col];
        float w3 = Wl[(k0 + 9) * 32 + col];

        uint32_t rb0 = cvt_f16x2(w1, w0);
        uint32_t rb1 = cvt_f16x2(w3, w2);
        sFRAG[idx] = ((u64)rb1 << 32) | rb0;
    }
    __syncthreads();

    const int wid  = tid >> 5;
    const int lane = tid & 31;
    const int g    = lane >> 2;
    const int q    = lane & 3;

    const float bias_out = sBOUT[0];

    for (int pair = blockIdx.x * NWARPS + wid; pair < npairs;
         pair += gridDim.x * NWARPS) {

        int base = pair * 32;
        int rA0 = base + g,      rA1 = base + 8 + g;
        int rB0 = base + 16 + g, rB1 = base + 24 + g;
        int cA0 = min(rA0, B - 1), cA1 = min(rA1, B - 1);
        int cB0 = min(rB0, B - 1), cB1 = min(rB1, B - 1);

        // acc holds RAW pre-activations at layer boundaries
        float acc0[16], acc1[16];

        // ---- layer 1 (6 -> 32), fp32 SIMT: raw preactivations ----
        {
            float x0[6], x1[6], x2[6], x3[6];
            const float* p0 = x + (long long)cA0 * 6;
            const float* p1 = x + (long long)cA1 * 6;
            const float* p2 = x + (long long)cB0 * 6;
            const float* p3 = x + (long long)cB1 * 6;
            #pragma unroll
            for (int i = 0; i < 6; i++) {
                x0[i] = __ldg(p0 + i); x1[i] = __ldg(p1 + i);
                x2[i] = __ldg(p2 + i); x3[i] = __ldg(p3 + i);
            }
            #pragma unroll
            for (int nb = 0; nb < 4; nb++) {
                int c0 = nb * 8 + q * 2;
                float b0 = sB1[c0], b1v = sB1[c0 + 1];
                float s00 = b0, s01 = b1v, s10 = b0, s11 = b1v;
                float t00 = b0, t01 = b1v, t10 = b0, t11 = b1v;
                #pragma unroll
                for (int i = 0; i < 6; i++) {
                    float w0 = sW1[i * 32 + c0], w1 = sW1[i * 32 + c0 + 1];
                    s00 += x0[i] * w0; s01 += x0[i] * w1;
                    s10 += x1[i] * w0; s11 += x1[i] * w1;
                    t00 += x2[i] * w0; t01 += x2[i] * w1;
                    t10 += x3[i] * w0; t11 += x3[i] * w1;
                }
                acc0[nb*4+0] = s00; acc0[nb*4+1] = s01;
                acc0[nb*4+2] = s10; acc0[nb*4+3] = s11;
                acc1[nb*4+0] = t00; acc1[nb*4+1] = t01;
                acc1[nb*4+2] = t10; acc1[nb*4+3] = t11;
            }
        }

        // ---- 19 hidden layers via fp16 HMMA ----
        for (int l = 0; l < 19; l++) {
            // hoist the 8 B-fragment LDS (hidden under the packs below)
            const u64* fl = sFRAG + l * 256 + lane;
            u64 Bf[8];
            #pragma unroll
            for (int c = 0; c < 8; c++) Bf[c] = fl[c * 32];

            uint32_t a0v[8], a1v[8];
            ss_pack(acc0, a0v);
            ss_pack(acc1, a1v);

            const float2* blp = (const float2*)(sBH + l * 32);

            // ks0: bias-init, 8 independent MMAs (2 tiles x 4 nb)
            #pragma unroll
            for (int nb = 0; nb < 4; nb++) {
                u64 w = Bf[nb];
                uint32_t b0 = (uint32_t)w, b1 = (uint32_t)(w >> 32);
                float2 bb = blp[nb * 4 + q];
                mma_f16_init(acc0 + nb * 4, a0v[0], a0v[1], a0v[2], a0v[3],
                             b0, b1, bb.x, bb.y);
                mma_f16_init(acc1 + nb * 4, a1v[0], a1v[1], a1v[2], a1v[3],
                             b0, b1, bb.x, bb.y);
            }
            // ks1: accumulate, 8 independent MMAs
            #pragma unroll
            for (int nb = 0; nb < 4; nb++) {
                u64 w = Bf[4 + nb];
                uint32_t b0 = (uint32_t)w, b1 = (uint32_t)(w >> 32);
                mma_f16(acc0 + nb * 4, a0v[4], a0v[5], a0v[6], a0v[7], b0, b1);
                mma_f16(acc1 + nb * 4, a1v[4], a1v[5], a1v[6], a1v[7], b0, b1);
            }
        }

        // ---- final softsign + output layer (32 -> 1) + quad reduction ----
        float pA0 = 0.0f, pA1 = 0.0f, pB0 = 0.0f, pB1 = 0.0f;
        #pragma unroll
        for (int nb = 0; nb < 4; nb++) {
            int c0 = nb * 8 + q * 2;
            float w0 = sWOUT[c0], w1 = sWOUT[c0 + 1];
            pA0 += softsign_f(acc0[nb*4+0]) * w0 + softsign_f(acc0[nb*4+1]) * w1;
            pA1 += softsign_f(acc0[nb*4+2]) * w0 + softsign_f(acc0[nb*4+3]) * w1;
            pB0 += softsign_f(acc1[nb*4+0]) * w0 + softsign_f(acc1[nb*4+1]) * w1;
            pB1 += softsign_f(acc1[nb*4+2]) * w0 + softsign_f(acc1[nb*4+3]) * w1;
        }
        pA0 += __shfl_xor_sync(0xFFFFFFFFu, pA0, 1);
        pA0 += __shfl_xor_sync(0xFFFFFFFFu, pA0, 2);
        pA1 += __shfl_xor_sync(0xFFFFFFFFu, pA1, 1);
        pA1 += __shfl_xor_sync(0xFFFFFFFFu, pA1, 2);
        pB0 += __shfl_xor_sync(0xFFFFFFFFu, pB0, 1);
        pB0 += __shfl_xor_sync(0xFFFFFFFFu, pB0, 2);
        pB1 += __shfl_xor_sync(0xFFFFFFFFu, pB1, 1);
        pB1 += __shfl_xor_sync(0xFFFFFFFFu, pB1, 2);
        if (q == 0) {
            if (rA0 < B) out[rA0] = pA0 + bias_out;
            if (rA1 < B) out[rA1] = pA1 + bias_out;
            if (rB0 < B) out[rB0] = pB0 + bias_out;
            if (rB1 < B) out[rB1] = pB1 + bias_out;
        }
    }
}

extern "C" void kernel_launch(void* const* d_in, const int* in_sizes, int n_in,
                              void* d_out, int out_size)
{
    const float* x    = (const float*)d_in[0];
    const float* W1   = (const float*)d_in[1];
    const float* b1   = (const float*)d_in[2];
    const float* Wh   = (const float*)d_in[3];
    const float* bh   = (const float*)d_in[4];
    const float* Wout = (const float*)d_in[5];
    const float* bout = (const float*)d_in[6];
    float* out = (float*)d_out;

    int B = in_sizes[0] / 6;
    int npairs = (B + 31) / 32;

    cudaFuncSetAttribute(actuator_hmma_kernel,
                         cudaFuncAttributeMaxDynamicSharedMemorySize, SM_TOTAL);

    int grid = 296;   // persistent: 2 CTAs/SM x 148 SMs
    actuator_hmma_kernel<<<grid, NTHREADS, SM_TOTAL>>>(
        x, W1, b1, Wh, bh, Wout, bout, out, B, npairs);
}